// round 10
// baseline (speedup 1.0000x reference)
#include <cuda_runtime.h>
#include <cuda_fp16.h>
#include <cstdint>

// Problem dims (fixed)
#define FDIM 1024
#define CDIM 128
#define BDIM 2048

#define BM 16
#define BN 128
#define BK 128
#define NITER (FDIM / BK)       // 8
#define NSTAGE 3
#define THREADS 512

// ---------------- scratch ----------------
__device__ __half g_b[CDIM * FDIM];   // softmax(w) fp16, [c][k] k-major

// ---------------- helpers ----------------
__device__ __forceinline__ uint32_t smem_u32(const void* p) {
    uint32_t a;
    asm("{ .reg .u64 t; cvta.to.shared.u64 t, %1; cvt.u32.u64 %0, t; }" : "=r"(a) : "l"(p));
    return a;
}
// 256B-row tile, 16B-granularity XOR swizzle
__device__ __forceinline__ uint32_t swz256(uint32_t row, uint32_t colByte) {
    return row * 256u + (colByte ^ ((row & 7u) << 4));
}
#define CP_ASYNC16(sm, g) asm volatile("cp.async.cg.shared.global [%0], [%1], 16;" :: "r"(sm), "l"(g) : "memory")
#define CP_COMMIT()       asm volatile("cp.async.commit_group;" ::: "memory")
#define CP_WAIT1()        asm volatile("cp.async.wait_group 1;" ::: "memory")
#define CP_WAIT0()        asm volatile("cp.async.wait_group 0;" ::: "memory")

#define LDMATRIX_X4(r0, r1, r2, r3, addr)                                        \
    asm volatile("ldmatrix.sync.aligned.m8n8.x4.shared.b16 {%0,%1,%2,%3}, [%4];" \
                 : "=r"(r0), "=r"(r1), "=r"(r2), "=r"(r3) : "r"(addr))

#define MMA_F16(d, a, b)                                                         \
    asm volatile("mma.sync.aligned.m16n8k16.row.col.f32.f16.f16.f32 "            \
                 "{%0,%1,%2,%3}, {%4,%5,%6,%7}, {%8,%9}, {%0,%1,%2,%3};"         \
                 : "+f"((d)[0]), "+f"((d)[1]), "+f"((d)[2]), "+f"((d)[3])        \
                 : "r"((a)[0]), "r"((a)[1]), "r"((a)[2]), "r"((a)[3]),           \
                   "r"((b)[0]), "r"((b)[1]))

// ---------------------------------------------------------------------------
// Kernel 1: warp-per-class softmax(weight) -> g_b fp16 (shfl-only)
// ---------------------------------------------------------------------------
__global__ void __launch_bounds__(256) prep_w_kernel(const float* __restrict__ w) {
    const int gw   = (blockIdx.x * 256 + threadIdx.x) >> 5;   // class 0..127
    const int lane = threadIdx.x & 31;
    const float* row = w + (size_t)gw * FDIM;

    float4 v[8];
    float m = -1e30f;
#pragma unroll
    for (int j = 0; j < 8; j++) {
        v[j] = *reinterpret_cast<const float4*>(row + j * 128 + lane * 4);
        m = fmaxf(m, fmaxf(fmaxf(v[j].x, v[j].y), fmaxf(v[j].z, v[j].w)));
    }
#pragma unroll
    for (int s = 16; s > 0; s >>= 1) m = fmaxf(m, __shfl_xor_sync(0xffffffffu, m, s));

    float sum = 0.0f;
#pragma unroll
    for (int j = 0; j < 8; j++) {
        v[j].x = __expf(v[j].x - m); v[j].y = __expf(v[j].y - m);
        v[j].z = __expf(v[j].z - m); v[j].w = __expf(v[j].w - m);
        sum += (v[j].x + v[j].y) + (v[j].z + v[j].w);
    }
#pragma unroll
    for (int s = 16; s > 0; s >>= 1) sum += __shfl_xor_sync(0xffffffffu, sum, s);
    const float inv = 1.0f / sum;

#pragma unroll
    for (int j = 0; j < 8; j++) {
        __half2 h01 = __floats2half2_rn(v[j].x * inv, v[j].y * inv);
        __half2 h23 = __floats2half2_rn(v[j].z * inv, v[j].w * inv);
        uint2 pv = make_uint2(*reinterpret_cast<uint32_t*>(&h01),
                              *reinterpret_cast<uint32_t*>(&h23));
        *reinterpret_cast<uint2*>(g_b + (size_t)gw * FDIM + j * 128 + lane * 4) = pv;
    }
}

// ---------------------------------------------------------------------------
// Kernel 2: fused exp->fp16 HMMA GEMM->log. 128 CTAs x 512 threads (16 warps).
// Warp specialization: 4 k-chunks (kc=warp>>2) x 4 n-warps (nw=warp&3).
// Warp tile 16x32; each warp handles ksteps [kc*2, kc*2+2) of each BK=128
// stage. Per warp per k16: 3 LDSM.x4 -> 4 HMMA. Epilogue: kc>0 warps STS
// partials, kc=0 warps reduce + log + store.
// ---------------------------------------------------------------------------
#define OFF_A 0
#define OFF_B 4096
#define STAGE_BYTES 36864          // A 16x256B (4KB) + B 128x256B (32KB)
#define RED_OFF (NSTAGE * STAGE_BYTES)            // 110592
#define SMEM_TOTAL (RED_OFF + 12 * 2048)          // +24KB reduce buf = 135168

__device__ __forceinline__ void load_x(float4& xv, const float* __restrict__ xbase,
                                       int kOff, int tid) {
    const uint32_t row = (uint32_t)tid >> 5;    // 0..15
    const uint32_t c4  = (uint32_t)tid & 31;    // float4 within 128-col row
    xv = *reinterpret_cast<const float4*>(xbase + (size_t)row * FDIM + kOff + c4 * 4);
}

__device__ __forceinline__ void convert_x(char* stage, const float4 xv, int tid) {
    const uint32_t row = (uint32_t)tid >> 5;
    const uint32_t c4  = (uint32_t)tid & 31;
    __half2 h01 = __floats2half2_rn(__expf(xv.x), __expf(xv.y));
    __half2 h23 = __floats2half2_rn(__expf(xv.z), __expf(xv.w));
    uint2 pv = make_uint2(*reinterpret_cast<uint32_t*>(&h01),
                          *reinterpret_cast<uint32_t*>(&h23));
    const uint32_t byteOff = swz256(row, (c4 >> 1) * 16) + (c4 & 1) * 8;
    *reinterpret_cast<uint2*>(stage + OFF_A + byteOff) = pv;
}

__device__ __forceinline__ void issue_b(uint32_t stageBase, int kOff, int tid) {
#pragma unroll
    for (int t = 0; t < 4; t++) {
        const int idx = tid + t * THREADS;          // 0..2047
        const uint32_t row = (uint32_t)idx >> 4;    // 0..127
        const uint32_t c16 = (uint32_t)idx & 15;    // 16B chunk (8 fp16)
        const __half* src = g_b + (size_t)row * FDIM + kOff + c16 * 8;
        CP_ASYNC16(stageBase + OFF_B + swz256(row, c16 * 16), src);
    }
    CP_COMMIT();
}

__global__ void __launch_bounds__(THREADS) mma_kernel(const float* __restrict__ x,
                                                      float* __restrict__ out) {
    extern __shared__ char smem[];
    const uint32_t sbase = smem_u32(smem);
    const int tid  = threadIdx.x;
    const int warp = tid >> 5;
    const int lane = tid & 31;
    const int nw   = warp & 3;     // n-warp: cols [nw*32, nw*32+32)
    const int kc   = warp >> 2;    // k-chunk: ksteps [kc*2, kc*2+2) per stage

    const int mtile = (int)blockIdx.x;   // 0..127

    float acc[2][4][4];            // [local kstep j][ni]
#pragma unroll
    for (int p = 0; p < 2; p++)
#pragma unroll
        for (int j = 0; j < 4; j++)
#pragma unroll
            for (int e = 0; e < 4; e++) acc[p][j][e] = 0.0f;

    // ldmatrix lane address components
    const uint32_t aRow = (lane & 7) + ((lane >> 3) & 1) * 8;        // 0..15
    const uint32_t aCol = (lane >> 4) * 16;
    const uint32_t bRow = nw * 32 + ((lane >> 4) & 1) * 8 + (lane & 7);
    const uint32_t bCol = ((lane >> 3) & 1) * 16;

    const float* xbase = x + (size_t)mtile * BM * FDIM;

    float4 xv, xnv;

    // Prologue: stages 0,1 filled; x for stage 2 preloaded
    load_x(xv, xbase, 0, tid);
    convert_x(smem + 0 * STAGE_BYTES, xv, tid);
    issue_b(sbase + 0 * STAGE_BYTES, 0, tid);
    load_x(xv, xbase, BK, tid);
    convert_x(smem + 1 * STAGE_BYTES, xv, tid);
    issue_b(sbase + 1 * STAGE_BYTES, BK, tid);
    load_x(xv, xbase, 2 * BK, tid);
    CP_WAIT1();
    __syncthreads();

#pragma unroll
    for (int it = 0; it < NITER; it++) {
        const uint32_t cur = sbase + (uint32_t)(it % 3) * STAGE_BYTES;
        const bool issue = (it + 2 < NITER);

        if (issue) {
            if (it + 3 < NITER) load_x(xnv, xbase, (it + 3) * BK, tid);
            const int s2 = (it + 2) % 3;
            convert_x(smem + s2 * STAGE_BYTES, xv, tid);
            issue_b(sbase + (uint32_t)s2 * STAGE_BYTES, (it + 2) * BK, tid);
        }

#pragma unroll
        for (int j = 0; j < 2; j++) {
            const uint32_t kb = (uint32_t)(kc * 2 + j) * 32;
            uint32_t a[4], b0[4], b1[4];
            LDMATRIX_X4(a[0], a[1], a[2], a[3],     cur + OFF_A + swz256(aRow, kb + aCol));
            LDMATRIX_X4(b0[0], b0[1], b0[2], b0[3], cur + OFF_B + swz256(bRow, kb + bCol));
            LDMATRIX_X4(b1[0], b1[1], b1[2], b1[3], cur + OFF_B + swz256(bRow + 16, kb + bCol));
            MMA_F16(acc[j][0], a, b0);
            MMA_F16(acc[j][1], a, b0 + 2);
            MMA_F16(acc[j][2], a, b1);
            MMA_F16(acc[j][3], a, b1 + 2);
        }

        if (it + 1 < NITER) {
            if (issue) { CP_WAIT1(); } else { CP_WAIT0(); }
            __syncthreads();
        }
        if (it + 3 < NITER) xv = xnv;
    }

    // ---- epilogue: 4-way k reduction ----
    float s[4][4];
#pragma unroll
    for (int j = 0; j < 4; j++)
#pragma unroll
        for (int e = 0; e < 4; e++) s[j][e] = acc[0][j][e] + acc[1][j][e];

    float* red = reinterpret_cast<float*>(smem + RED_OFF);
    const uint32_t r0 = lane >> 2;              // 0..7
    const uint32_t cb = (lane & 3) * 2;
    __syncthreads();
    if (kc > 0) {
        float* dst = red + (size_t)((kc - 1) * 4 + nw) * 512;
#pragma unroll
        for (int ni = 0; ni < 4; ni++) {
            const uint32_t c = ni * 8 + cb;
            *reinterpret_cast<float2*>(dst + r0 * 32 + c)       = make_float2(s[ni][0], s[ni][1]);
            *reinterpret_cast<float2*>(dst + (r0 + 8) * 32 + c) = make_float2(s[ni][2], s[ni][3]);
        }
    }
    __syncthreads();
    if (kc == 0) {
#pragma unroll
        for (int p = 0; p < 3; p++) {
            const float* src = red + (size_t)(p * 4 + nw) * 512;
#pragma unroll
            for (int ni = 0; ni < 4; ni++) {
                const uint32_t c = ni * 8 + cb;
                float2 v0 = *reinterpret_cast<const float2*>(src + r0 * 32 + c);
                float2 v1 = *reinterpret_cast<const float2*>(src + (r0 + 8) * 32 + c);
                s[ni][0] += v0.x; s[ni][1] += v0.y;
                s[ni][2] += v1.x; s[ni][3] += v1.y;
            }
        }
#pragma unroll
        for (int ni = 0; ni < 4; ni++) {
            const int m = mtile * BM + (int)r0;
            const int n = nw * 32 + ni * 8 + (int)cb;
            *reinterpret_cast<float2*>(out + (size_t)m * CDIM + n) =
                make_float2(__logf(s[ni][0]), __logf(s[ni][1]));
            *reinterpret_cast<float2*>(out + (size_t)(m + 8) * CDIM + n) =
                make_float2(__logf(s[ni][2]), __logf(s[ni][3]));
        }
    }
}

// ---------------------------------------------------------------------------
extern "C" void kernel_launch(void* const* d_in, const int* in_sizes, int n_in,
                              void* d_out, int out_size) {
    const float* x = (const float*)d_in[0];
    const float* w = (const float*)d_in[1];
    if (n_in >= 2 && in_sizes[0] == CDIM * FDIM && in_sizes[1] == BDIM * FDIM) {
        w = (const float*)d_in[0];
        x = (const float*)d_in[1];
    }
    float* out = (float*)d_out;

    static bool attr_set = false;
    if (!attr_set) {
        cudaFuncSetAttribute(mma_kernel, cudaFuncAttributeMaxDynamicSharedMemorySize, SMEM_TOTAL);
        attr_set = true;
    }

    prep_w_kernel<<<CDIM / 8, 256>>>(w);
    mma_kernel<<<BDIM / BM, THREADS, SMEM_TOTAL>>>(x, out);
}